// round 13
// baseline (speedup 1.0000x reference)
#include <cuda_runtime.h>

#define NNODES 50000
#define DD 16
#define BB 32
#define NPAIR 16
#define NDRVN 500
#define FEAT 5
#define NMID 5

typedef unsigned long long u64;

// State buffers
__device__ float g_zA[NNODES * BB];
__device__ float g_zB[NNODES * BB];
__device__ float g_zf[NDRVN * BB];

// Packed-weight staging (filled by pack_kernel, then copied to __constant__)
// layout: [0:15) wf, [15:20) bf, [20:245) wm, [245:270) bm, [270:285) wl, [285] bl
#define PK_TOTAL 286
__device__ u64 g_wstage[PK_TOTAL];

// Scalar weights in constant memory
__constant__ float c_wf[FEAT * 3];
__constant__ float c_bf[FEAT];
__constant__ float c_wm[NMID * FEAT * FEAT * 3];
__constant__ float c_bm[NMID * FEAT];
__constant__ float c_wl[FEAT * 3];
__constant__ float c_bl[1];

// Packed {w,w} weights in constant memory
__constant__ u64 c_pwf[FEAT * 3];
__constant__ u64 c_pbf[FEAT];
__constant__ u64 c_pwm[NMID * FEAT * FEAT * 3];
__constant__ u64 c_pbm[NMID * FEAT];
__constant__ u64 c_pwl[FEAT * 3];
__constant__ u64 c_pbl[1];

// ---------------------------------------------------------------------------
// Packed f32x2 helpers
// ---------------------------------------------------------------------------
__device__ __forceinline__ u64 ffma2(u64 a, u64 b, u64 c) {
    u64 d;
    asm("fma.rn.f32x2 %0, %1, %2, %3;" : "=l"(d) : "l"(a), "l"(b), "l"(c));
    return d;
}
__device__ __forceinline__ u64 add2(u64 a, u64 b) {
    u64 d;
    asm("add.rn.f32x2 %0, %1, %2;" : "=l"(d) : "l"(a), "l"(b));
    return d;
}
__device__ __forceinline__ u64 mul2(u64 a, u64 b) {
    u64 d;
    asm("mul.rn.f32x2 %0, %1, %2;" : "=l"(d) : "l"(a), "l"(b));
    return d;
}
__device__ __forceinline__ u64 relu2(u64 x) {
    unsigned lo, hi;
    asm("mov.b64 {%0,%1}, %2;" : "=r"(lo), "=r"(hi) : "l"(x));
    float a = fmaxf(__uint_as_float(lo), 0.0f);
    float b = fmaxf(__uint_as_float(hi), 0.0f);
    u64 r;
    asm("mov.b64 %0, {%1,%2};" : "=l"(r) : "r"(__float_as_uint(a)), "r"(__float_as_uint(b)));
    return r;
}

// ---------------------------------------------------------------------------
// Pack scalar weights into {w,w} u64 staging buffer (deterministic, on-graph)
// ---------------------------------------------------------------------------
__global__ void pack_kernel(const float* __restrict__ w_first, const float* __restrict__ b_first,
                            const float* __restrict__ w_mid,   const float* __restrict__ b_mid,
                            const float* __restrict__ w_last,  const float* __restrict__ b_last) {
    int t = threadIdx.x;
    float v;
    if (t < 15)       v = w_first[t];
    else if (t < 20)  v = b_first[t - 15];
    else if (t < 245) v = w_mid[t - 20];
    else if (t < 270) v = b_mid[t - 245];
    else if (t < 285) v = w_last[t - 270];
    else if (t == 285) v = b_last[0];
    else return;
    unsigned u = __float_as_uint(v);
    u64 r;
    asm("mov.b64 %0, {%1,%1};" : "=l"(r) : "r"(u));
    g_wstage[t] = r;
}

// ---------------------------------------------------------------------------
// Transpose x [B, N] -> g_zA [N, B]
// ---------------------------------------------------------------------------
__global__ void transpose_kernel(const float* __restrict__ x) {
    __shared__ float tile[32][33];
    int n0 = blockIdx.x * 32;
    int tx = threadIdx.x, ty = threadIdx.y;
    int n = n0 + tx;
    if (n < NNODES) tile[ty][tx] = x[ty * NNODES + n];
    __syncthreads();
    int n2 = n0 + ty;
    if (n2 < NNODES) g_zA[n2 * BB + tx] = tile[tx][ty];
}

// ===========================================================================
// VARIANT A (pass 1): FFMA2 packed, weights from __constant__ u64.  zA -> zB
// ===========================================================================
template <int WIN>
__device__ __forceinline__ void mid_layer_pk(u64 (&h)[FEAT][DD - 2], int L) {
    const u64* wbase = c_pwm + L * FEAT * FEAT * 3;
    const u64* bbase = c_pbm + L * FEAT;
    #pragma unroll
    for (int w = 0; w < WIN - 2; w++) {
        u64 tmp[FEAT];
        #pragma unroll
        for (int co = 0; co < FEAT; co++) {
            u64 a = bbase[co];
            #pragma unroll
            for (int ci = 0; ci < FEAT; ci++) {
                a = ffma2(wbase[(co * FEAT + ci) * 3 + 0], h[ci][w + 0], a);
                a = ffma2(wbase[(co * FEAT + ci) * 3 + 1], h[ci][w + 1], a);
                a = ffma2(wbase[(co * FEAT + ci) * 3 + 2], h[ci][w + 2], a);
            }
            tmp[co] = relu2(a);
        }
        #pragma unroll
        for (int co = 0; co < FEAT; co++) h[co][w] = tmp[co];
    }
}

__global__ void __launch_bounds__(128)
pass1_packed(const int* __restrict__ nbr) {
    const u64* __restrict__ zin = (const u64*)g_zA;
    u64* __restrict__ zout      = (u64*)g_zB;

    unsigned gid = blockIdx.x * blockDim.x + threadIdx.x;
    if (gid >= (unsigned)NNODES * NPAIR) return;
    int n = gid >> 4;
    int p = gid & 15;

    u64 v[DD];
    const int* nb = nbr + n * DD;
    #pragma unroll
    for (int d = 0; d < DD; d++) {
        int idx = __ldg(&nb[d]);
        v[d] = __ldg(&zin[idx * NPAIR + p]);
    }

    u64 h[FEAT][DD - 2];
    #pragma unroll
    for (int c = 0; c < FEAT; c++) {
        #pragma unroll
        for (int w = 0; w < DD - 2; w++) {
            u64 a = c_pbf[c];
            a = ffma2(c_pwf[c * 3 + 0], v[w + 0], a);
            a = ffma2(c_pwf[c * 3 + 1], v[w + 1], a);
            a = ffma2(c_pwf[c * 3 + 2], v[w + 2], a);
            h[c][w] = relu2(a);
        }
    }

    mid_layer_pk<14>(h, 0);
    mid_layer_pk<12>(h, 1);
    mid_layer_pk<10>(h, 2);
    mid_layer_pk<8>(h, 3);
    mid_layer_pk<6>(h, 4);

    u64 o[2];
    #pragma unroll
    for (int w = 0; w < 2; w++) {
        u64 a = c_pbl[0];
        #pragma unroll
        for (int ci = 0; ci < FEAT; ci++) {
            a = ffma2(c_pwl[ci * 3 + 0], h[ci][w + 0], a);
            a = ffma2(c_pwl[ci * 3 + 1], h[ci][w + 1], a);
            a = ffma2(c_pwl[ci * 3 + 2], h[ci][w + 2], a);
        }
        o[w] = relu2(a);
    }
    u64 half;
    {
        unsigned u = __float_as_uint(0.5f);
        asm("mov.b64 %0, {%1,%1};" : "=l"(half) : "r"(u));
    }
    zout[n * NPAIR + p] = mul2(add2(o[0], o[1]), half);
}

// ===========================================================================
// VARIANT B: scalar const body (proven R11, 210us)
// ===========================================================================
template <int WIN, int AW, int BW>
__device__ __forceinline__ void mid_layer_c(const float (&hin)[FEAT][AW],
                                            float (&hout)[FEAT][BW],
                                            int L) {
    const float* wbase = c_wm + L * FEAT * FEAT * 3;
    const float* bbase = c_bm + L * FEAT;
    #pragma unroll
    for (int co = 0; co < FEAT; co++) {
        float bias = bbase[co];
        #pragma unroll
        for (int w = 0; w < WIN - 2; w++) {
            float a = bias;
            #pragma unroll
            for (int ci = 0; ci < FEAT; ci++) {
                a = fmaf(wbase[(co * FEAT + ci) * 3 + 0], hin[ci][w + 0], a);
                a = fmaf(wbase[(co * FEAT + ci) * 3 + 1], hin[ci][w + 1], a);
                a = fmaf(wbase[(co * FEAT + ci) * 3 + 2], hin[ci][w + 2], a);
            }
            hout[co][w] = fmaxf(a, 0.0f);
        }
    }
}

__device__ __forceinline__ float conv_stack_c(const float (&v)[DD]) {
    float hA[FEAT][14];
    #pragma unroll
    for (int c = 0; c < FEAT; c++) {
        float bias = c_bf[c];
        #pragma unroll
        for (int w = 0; w < 14; w++) {
            float a = bias;
            a = fmaf(c_wf[c * 3 + 0], v[w + 0], a);
            a = fmaf(c_wf[c * 3 + 1], v[w + 1], a);
            a = fmaf(c_wf[c * 3 + 2], v[w + 2], a);
            hA[c][w] = fmaxf(a, 0.0f);
        }
    }

    float hB[FEAT][12];
    mid_layer_c<14>(hA, hB, 0);
    mid_layer_c<12>(hB, hA, 1);
    mid_layer_c<10>(hA, hB, 2);
    mid_layer_c<8>(hB, hA, 3);
    mid_layer_c<6>(hA, hB, 4);

    float o[2];
    #pragma unroll
    for (int w = 0; w < 2; w++) {
        float a = c_bl[0];
        #pragma unroll
        for (int ci = 0; ci < FEAT; ci++) {
            a = fmaf(c_wl[ci * 3 + 0], hB[ci][w + 0], a);
            a = fmaf(c_wl[ci * 3 + 1], hB[ci][w + 1], a);
            a = fmaf(c_wl[ci * 3 + 2], hB[ci][w + 2], a);
        }
        o[w] = fmaxf(a, 0.0f);
    }
    return 0.5f * (o[0] + o[1]);
}

// Pass 2: scalar const, zB -> zA
__global__ void __launch_bounds__(128)
pass2_scalar(const int* __restrict__ nbr) {
    unsigned gid = blockIdx.x * blockDim.x + threadIdx.x;
    int n = gid >> 5;
    int b = gid & 31;

    float v[DD];
    const int* nb = nbr + n * DD;
    #pragma unroll
    for (int d = 0; d < DD; d++) {
        int idx = __ldg(&nb[d]);
        v[d] = __ldg(&g_zB[idx * BB + b]);
    }
    g_zA[n * BB + b] = conv_stack_c(v);
}

// ---------------------------------------------------------------------------
// Fused passes 3+4: block = one driver. 512 threads.
// Phase 1: thread (j,b) computes z3 for neighbor slot j, batch b -> smem.
// Phase 2: threads b<32 compute the driver's z4 from smem.
// ---------------------------------------------------------------------------
__global__ void __launch_bounds__(512)
pass34_fused(const int* __restrict__ nbr, const int* __restrict__ drivers) {
    __shared__ float s34[DD][BB];
    int d = blockIdx.x;
    int tid = threadIdx.x;
    int j = tid >> 5;
    int b = tid & 31;

    int m = __ldg(&nbr[__ldg(&drivers[d]) * DD + j]);

    float v[DD];
    const int* nb = nbr + m * DD;
    #pragma unroll
    for (int k = 0; k < DD; k++) {
        int idx = __ldg(&nb[k]);
        v[k] = __ldg(&g_zA[idx * BB + b]);
    }
    s34[j][b] = conv_stack_c(v);
    __syncthreads();

    if (tid < BB) {
        float v2[DD];
        #pragma unroll
        for (int k = 0; k < DD; k++) v2[k] = s34[k][tid];
        g_zf[d * BB + tid] = conv_stack_c(v2);
    }
}

// ---------------------------------------------------------------------------
__global__ void zero_kernel(float4* __restrict__ out, int n4) {
    int i = blockIdx.x * blockDim.x + threadIdx.x;
    if (i < n4) out[i] = make_float4(0.f, 0.f, 0.f, 0.f);
}

// ---------------------------------------------------------------------------
// Masked softmax over driver columns; reads g_zf [500][B]
// ---------------------------------------------------------------------------
__global__ void softmax_kernel(const int* __restrict__ drivers,
                               float* __restrict__ out) {
    __shared__ float red[512];
    int b = blockIdx.x;
    int t = threadIdx.x;

    float myv = 0.0f;
    int drv = -1;
    float mval = -INFINITY;
    if (t < NDRVN) {
        drv = drivers[t];
        myv = g_zf[t * BB + b];
        mval = myv;
    }
    red[t] = mval;
    __syncthreads();
    #pragma unroll
    for (int s = 256; s > 0; s >>= 1) {
        if (t < s) red[t] = fmaxf(red[t], red[t + s]);
        __syncthreads();
    }
    float m = fmaxf(red[0], 0.0f);
    __syncthreads();

    float e = (t < NDRVN) ? expf(myv - m) : 0.0f;
    red[t] = e;
    __syncthreads();
    #pragma unroll
    for (int s = 256; s > 0; s >>= 1) {
        if (t < s) red[t] += red[t + s];
        __syncthreads();
    }
    float Z = red[0] + (float)(NNODES - NDRVN) * expf(-m);

    if (t < NDRVN) out[b * NNODES + drv] = e / Z;
}

// ---------------------------------------------------------------------------
extern "C" void kernel_launch(void* const* d_in, const int* in_sizes, int n_in,
                              void* d_out, int out_size) {
    const float* x       = (const float*)d_in[0];
    const int*   nbr     = (const int*)  d_in[1];
    const int*   drivers = (const int*)  d_in[2];
    const float* w_first = (const float*)d_in[4];
    const float* b_first = (const float*)d_in[5];
    const float* w_mid   = (const float*)d_in[6];
    const float* b_mid   = (const float*)d_in[7];
    const float* w_last  = (const float*)d_in[8];
    const float* b_last  = (const float*)d_in[9];
    float* out = (float*)d_out;

    // Scalar weights -> const (graph-capturable D2D copies)
    cudaMemcpyToSymbolAsync(c_wf, w_first, FEAT * 3 * sizeof(float), 0, cudaMemcpyDeviceToDevice);
    cudaMemcpyToSymbolAsync(c_bf, b_first, FEAT * sizeof(float), 0, cudaMemcpyDeviceToDevice);
    cudaMemcpyToSymbolAsync(c_wm, w_mid, NMID * FEAT * FEAT * 3 * sizeof(float), 0, cudaMemcpyDeviceToDevice);
    cudaMemcpyToSymbolAsync(c_bm, b_mid, NMID * FEAT * sizeof(float), 0, cudaMemcpyDeviceToDevice);
    cudaMemcpyToSymbolAsync(c_wl, w_last, FEAT * 3 * sizeof(float), 0, cudaMemcpyDeviceToDevice);
    cudaMemcpyToSymbolAsync(c_bl, b_last, sizeof(float), 0, cudaMemcpyDeviceToDevice);

    // Packed weights: pack kernel -> staging, then staging -> const (D2D)
    pack_kernel<<<1, 288>>>(w_first, b_first, w_mid, b_mid, w_last, b_last);
    void* stage_ptr = nullptr;
    cudaGetSymbolAddress(&stage_ptr, g_wstage);
    const u64* st = (const u64*)stage_ptr;
    cudaMemcpyToSymbolAsync(c_pwf, st + 0,   15 * sizeof(u64), 0, cudaMemcpyDeviceToDevice);
    cudaMemcpyToSymbolAsync(c_pbf, st + 15,   5 * sizeof(u64), 0, cudaMemcpyDeviceToDevice);
    cudaMemcpyToSymbolAsync(c_pwm, st + 20, 225 * sizeof(u64), 0, cudaMemcpyDeviceToDevice);
    cudaMemcpyToSymbolAsync(c_pbm, st + 245, 25 * sizeof(u64), 0, cudaMemcpyDeviceToDevice);
    cudaMemcpyToSymbolAsync(c_pwl, st + 270, 15 * sizeof(u64), 0, cudaMemcpyDeviceToDevice);
    cudaMemcpyToSymbolAsync(c_pbl, st + 285,  1 * sizeof(u64), 0, cudaMemcpyDeviceToDevice);

    // Independent prologue
    int n4 = NNODES * BB / 4;
    zero_kernel<<<(n4 + 255) / 256, 256>>>((float4*)out, n4);
    transpose_kernel<<<(NNODES + 31) / 32, dim3(32, 32)>>>(x);

    const int blk = 128;
    const int grid_pk = (NNODES * NPAIR + blk - 1) / blk;
    const int grid_sc = (NNODES * BB + blk - 1) / blk;

    pass1_packed<<<grid_pk, blk>>>(nbr);     // A: packed-const  zA -> zB
    pass2_scalar<<<grid_sc, blk>>>(nbr);     // B: scalar-const  zB -> zA

    pass34_fused<<<NDRVN, 512>>>(nbr, drivers);

    softmax_kernel<<<BB, 512>>>(drivers, out);
}

// round 14
// speedup vs baseline: 1.0493x; 1.0493x over previous
#include <cuda_runtime.h>

#define NNODES 50000
#define DD 16
#define BB 32
#define NDRVN 500
#define FEAT 5
#define NMID 5

// State buffers
__device__ float g_zA[NNODES * BB];
__device__ float g_zB[NNODES * BB];
__device__ float g_zf[NDRVN * BB];

// Weights in constant memory (filled by async D2D copies in kernel_launch)
__constant__ float c_wf[FEAT * 3];
__constant__ float c_bf[FEAT];
__constant__ float c_wm[NMID * FEAT * FEAT * 3];
__constant__ float c_bm[NMID * FEAT];
__constant__ float c_wl[FEAT * 3];
__constant__ float c_bl[1];

// ---------------------------------------------------------------------------
// Transpose x [B, N] -> g_zA [N, B]
// ---------------------------------------------------------------------------
__global__ void transpose_kernel(const float* __restrict__ x) {
    __shared__ float tile[32][33];
    int n0 = blockIdx.x * 32;
    int tx = threadIdx.x, ty = threadIdx.y;
    int n = n0 + tx;
    if (n < NNODES) tile[ty][tx] = x[ty * NNODES + n];
    __syncthreads();
    int n2 = n0 + ty;
    if (n2 < NNODES) g_zA[n2 * BB + tx] = tile[tx][ty];
}

// ===========================================================================
// Constant-weight scalar conv stack (proven fastest body: R11, 210us/pass)
// ===========================================================================
template <int WIN, int AW, int BW>
__device__ __forceinline__ void mid_layer_c(const float (&hin)[FEAT][AW],
                                            float (&hout)[FEAT][BW],
                                            int L) {
    const float* wbase = c_wm + L * FEAT * FEAT * 3;
    const float* bbase = c_bm + L * FEAT;
    #pragma unroll
    for (int co = 0; co < FEAT; co++) {
        float bias = bbase[co];
        #pragma unroll
        for (int w = 0; w < WIN - 2; w++) {
            float a = bias;
            #pragma unroll
            for (int ci = 0; ci < FEAT; ci++) {
                a = fmaf(wbase[(co * FEAT + ci) * 3 + 0], hin[ci][w + 0], a);
                a = fmaf(wbase[(co * FEAT + ci) * 3 + 1], hin[ci][w + 1], a);
                a = fmaf(wbase[(co * FEAT + ci) * 3 + 2], hin[ci][w + 2], a);
            }
            hout[co][w] = fmaxf(a, 0.0f);
        }
    }
}

__device__ __forceinline__ float conv_stack_c(const float (&v)[DD]) {
    float hA[FEAT][14];
    #pragma unroll
    for (int c = 0; c < FEAT; c++) {
        float bias = c_bf[c];
        #pragma unroll
        for (int w = 0; w < 14; w++) {
            float a = bias;
            a = fmaf(c_wf[c * 3 + 0], v[w + 0], a);
            a = fmaf(c_wf[c * 3 + 1], v[w + 1], a);
            a = fmaf(c_wf[c * 3 + 2], v[w + 2], a);
            hA[c][w] = fmaxf(a, 0.0f);
        }
    }

    float hB[FEAT][12];
    mid_layer_c<14>(hA, hB, 0);
    mid_layer_c<12>(hB, hA, 1);
    mid_layer_c<10>(hA, hB, 2);
    mid_layer_c<8>(hB, hA, 3);
    mid_layer_c<6>(hA, hB, 4);

    float o[2];
    #pragma unroll
    for (int w = 0; w < 2; w++) {
        float a = c_bl[0];
        #pragma unroll
        for (int ci = 0; ci < FEAT; ci++) {
            a = fmaf(c_wl[ci * 3 + 0], hB[ci][w + 0], a);
            a = fmaf(c_wl[ci * 3 + 1], hB[ci][w + 1], a);
            a = fmaf(c_wl[ci * 3 + 2], hB[ci][w + 2], a);
        }
        o[w] = fmaxf(a, 0.0f);
    }
    return 0.5f * (o[0] + o[1]);
}

// ---------------------------------------------------------------------------
// Full pass: warp = node, lane = batch.  SRC=0: zA->zB, SRC=1: zB->zA
// ---------------------------------------------------------------------------
template <int SRC>
__global__ void __launch_bounds__(128)
pass_const(const int* __restrict__ nbr) {
    const float* __restrict__ zin = SRC == 0 ? g_zA : g_zB;
    float* __restrict__ zout      = SRC == 0 ? g_zB : g_zA;

    unsigned gid = blockIdx.x * blockDim.x + threadIdx.x;
    if (gid >= (unsigned)NNODES * BB) return;
    int n = gid >> 5;
    int b = gid & 31;

    float v[DD];
    const int* nb = nbr + n * DD;
    #pragma unroll
    for (int d = 0; d < DD; d++) {
        int idx = __ldg(&nb[d]);
        v[d] = __ldg(&zin[idx * BB + b]);
    }
    zout[n * BB + b] = conv_stack_c(v);
}

// ---------------------------------------------------------------------------
// Fused passes 3+4: block = one driver, 512 threads.
// Phase 1: thread (j,b) computes z3 for neighbor slot j, batch b -> smem.
// Phase 2: threads b<32 compute the driver's z4 from smem.
// ---------------------------------------------------------------------------
__global__ void __launch_bounds__(512)
pass34_fused(const int* __restrict__ nbr, const int* __restrict__ drivers) {
    __shared__ float s34[DD][BB];
    int d = blockIdx.x;
    int tid = threadIdx.x;
    int j = tid >> 5;
    int b = tid & 31;

    int m = __ldg(&nbr[__ldg(&drivers[d]) * DD + j]);

    float v[DD];
    const int* nb = nbr + m * DD;
    #pragma unroll
    for (int k = 0; k < DD; k++) {
        int idx = __ldg(&nb[k]);
        v[k] = __ldg(&g_zA[idx * BB + b]);
    }
    s34[j][b] = conv_stack_c(v);
    __syncthreads();

    if (tid < BB) {
        float v2[DD];
        #pragma unroll
        for (int k = 0; k < DD; k++) v2[k] = s34[k][tid];
        g_zf[d * BB + tid] = conv_stack_c(v2);
    }
}

// ---------------------------------------------------------------------------
__global__ void zero_kernel(float4* __restrict__ out, int n4) {
    int i = blockIdx.x * blockDim.x + threadIdx.x;
    if (i < n4) out[i] = make_float4(0.f, 0.f, 0.f, 0.f);
}

// ---------------------------------------------------------------------------
// Masked softmax over driver columns; reads g_zf [500][B]
// ---------------------------------------------------------------------------
__global__ void softmax_kernel(const int* __restrict__ drivers,
                               float* __restrict__ out) {
    __shared__ float red[512];
    int b = blockIdx.x;
    int t = threadIdx.x;

    float myv = 0.0f;
    int drv = -1;
    float mval = -INFINITY;
    if (t < NDRVN) {
        drv = drivers[t];
        myv = g_zf[t * BB + b];
        mval = myv;
    }
    red[t] = mval;
    __syncthreads();
    #pragma unroll
    for (int s = 256; s > 0; s >>= 1) {
        if (t < s) red[t] = fmaxf(red[t], red[t + s]);
        __syncthreads();
    }
    float m = fmaxf(red[0], 0.0f);
    __syncthreads();

    float e = (t < NDRVN) ? expf(myv - m) : 0.0f;
    red[t] = e;
    __syncthreads();
    #pragma unroll
    for (int s = 256; s > 0; s >>= 1) {
        if (t < s) red[t] += red[t + s];
        __syncthreads();
    }
    float Z = red[0] + (float)(NNODES - NDRVN) * expf(-m);

    if (t < NDRVN) out[b * NNODES + drv] = e / Z;
}

// ---------------------------------------------------------------------------
extern "C" void kernel_launch(void* const* d_in, const int* in_sizes, int n_in,
                              void* d_out, int out_size) {
    const float* x       = (const float*)d_in[0];
    const int*   nbr     = (const int*)  d_in[1];
    const int*   drivers = (const int*)  d_in[2];
    const float* w_first = (const float*)d_in[4];
    const float* b_first = (const float*)d_in[5];
    const float* w_mid   = (const float*)d_in[6];
    const float* b_mid   = (const float*)d_in[7];
    const float* w_last  = (const float*)d_in[8];
    const float* b_last  = (const float*)d_in[9];
    float* out = (float*)d_out;

    // Weights -> __constant__ (graph-capturable D2D memcpy nodes)
    cudaMemcpyToSymbolAsync(c_wf, w_first, FEAT * 3 * sizeof(float), 0, cudaMemcpyDeviceToDevice);
    cudaMemcpyToSymbolAsync(c_bf, b_first, FEAT * sizeof(float), 0, cudaMemcpyDeviceToDevice);
    cudaMemcpyToSymbolAsync(c_wm, w_mid, NMID * FEAT * FEAT * 3 * sizeof(float), 0, cudaMemcpyDeviceToDevice);
    cudaMemcpyToSymbolAsync(c_bm, b_mid, NMID * FEAT * sizeof(float), 0, cudaMemcpyDeviceToDevice);
    cudaMemcpyToSymbolAsync(c_wl, w_last, FEAT * 3 * sizeof(float), 0, cudaMemcpyDeviceToDevice);
    cudaMemcpyToSymbolAsync(c_bl, b_last, sizeof(float), 0, cudaMemcpyDeviceToDevice);

    // Independent prologue
    int n4 = NNODES * BB / 4;
    zero_kernel<<<(n4 + 255) / 256, 256>>>((float4*)out, n4);
    transpose_kernel<<<(NNODES + 31) / 32, dim3(32, 32)>>>(x);

    const int blk = 128;
    const int grid_sc = (NNODES * BB + blk - 1) / blk;

    // Passes 1-2: full graph, scalar constant-weight body.  zA -> zB -> zA
    pass_const<0><<<grid_sc, blk>>>(nbr);
    pass_const<1><<<grid_sc, blk>>>(nbr);

    // Passes 3+4 fused: drivers' neighborhood only
    pass34_fused<<<NDRVN, 512>>>(nbr, drivers);

    softmax_kernel<<<BB, 512>>>(drivers, out);
}

// round 15
// speedup vs baseline: 1.1211x; 1.0684x over previous
#include <cuda_runtime.h>

#define NNODES 50000
#define DD 16
#define BB 32
#define NDRVN 500
#define FEAT 5
#define NMID 5

// State buffers
__device__ float g_zA[NNODES * BB];
__device__ float g_zB[NNODES * BB];
__device__ float g_z3[NDRVN * DD * BB];
__device__ float g_zf[NDRVN * BB];

// Weights in constant memory (filled by async D2D copies in kernel_launch)
__constant__ float c_wf[FEAT * 3];
__constant__ float c_bf[FEAT];
__constant__ float c_wm[NMID * FEAT * FEAT * 3];
__constant__ float c_bm[NMID * FEAT];
__constant__ float c_wl[FEAT * 3];
__constant__ float c_bl[1];

// ---------------------------------------------------------------------------
// Transpose x [B, N] -> g_zA [N, B]
// ---------------------------------------------------------------------------
__global__ void transpose_kernel(const float* __restrict__ x) {
    __shared__ float tile[32][33];
    int n0 = blockIdx.x * 32;
    int tx = threadIdx.x, ty = threadIdx.y;
    int n = n0 + tx;
    if (n < NNODES) tile[ty][tx] = x[ty * NNODES + n];
    __syncthreads();
    int n2 = n0 + ty;
    if (n2 < NNODES) g_zA[n2 * BB + tx] = tile[tx][ty];
}

// ===========================================================================
// Constant-weight scalar conv stack (proven fastest body: 207-211us/pass)
// ===========================================================================
template <int WIN, int AW, int BW>
__device__ __forceinline__ void mid_layer_c(const float (&hin)[FEAT][AW],
                                            float (&hout)[FEAT][BW],
                                            int L) {
    const float* wbase = c_wm + L * FEAT * FEAT * 3;
    const float* bbase = c_bm + L * FEAT;
    #pragma unroll
    for (int co = 0; co < FEAT; co++) {
        float bias = bbase[co];
        #pragma unroll
        for (int w = 0; w < WIN - 2; w++) {
            float a = bias;
            #pragma unroll
            for (int ci = 0; ci < FEAT; ci++) {
                a = fmaf(wbase[(co * FEAT + ci) * 3 + 0], hin[ci][w + 0], a);
                a = fmaf(wbase[(co * FEAT + ci) * 3 + 1], hin[ci][w + 1], a);
                a = fmaf(wbase[(co * FEAT + ci) * 3 + 2], hin[ci][w + 2], a);
            }
            hout[co][w] = fmaxf(a, 0.0f);
        }
    }
}

__device__ __forceinline__ float conv_stack_c(const float (&v)[DD]) {
    float hA[FEAT][14];
    #pragma unroll
    for (int c = 0; c < FEAT; c++) {
        float bias = c_bf[c];
        #pragma unroll
        for (int w = 0; w < 14; w++) {
            float a = bias;
            a = fmaf(c_wf[c * 3 + 0], v[w + 0], a);
            a = fmaf(c_wf[c * 3 + 1], v[w + 1], a);
            a = fmaf(c_wf[c * 3 + 2], v[w + 2], a);
            hA[c][w] = fmaxf(a, 0.0f);
        }
    }

    float hB[FEAT][12];
    mid_layer_c<14>(hA, hB, 0);
    mid_layer_c<12>(hB, hA, 1);
    mid_layer_c<10>(hA, hB, 2);
    mid_layer_c<8>(hB, hA, 3);
    mid_layer_c<6>(hA, hB, 4);

    float o[2];
    #pragma unroll
    for (int w = 0; w < 2; w++) {
        float a = c_bl[0];
        #pragma unroll
        for (int ci = 0; ci < FEAT; ci++) {
            a = fmaf(c_wl[ci * 3 + 0], hB[ci][w + 0], a);
            a = fmaf(c_wl[ci * 3 + 1], hB[ci][w + 1], a);
            a = fmaf(c_wl[ci * 3 + 2], hB[ci][w + 2], a);
        }
        o[w] = fmaxf(a, 0.0f);
    }
    return 0.5f * (o[0] + o[1]);
}

// ---------------------------------------------------------------------------
// Full pass: warp = node, lane = batch.  SRC=0: zA->zB, SRC=1: zB->zA
// Grid covers exactly NNODES*BB threads — no bound check needed.
// ---------------------------------------------------------------------------
template <int SRC>
__global__ void __launch_bounds__(128)
pass_const(const int* __restrict__ nbr) {
    const float* __restrict__ zin = SRC == 0 ? g_zA : g_zB;
    float* __restrict__ zout      = SRC == 0 ? g_zB : g_zA;

    unsigned gid = blockIdx.x * blockDim.x + threadIdx.x;
    int n = gid >> 5;
    int b = gid & 31;

    float v[DD];
    const int* nb = nbr + n * DD;
    #pragma unroll
    for (int d = 0; d < DD; d++) {
        int idx = __ldg(&nb[d]);
        v[d] = __ldg(&zin[idx * BB + b]);
    }
    zout[n * BB + b] = conv_stack_c(v);
}

// ---------------------------------------------------------------------------
// Pass 3 (lite): z3 at the 500x16 driver-neighbor slots, reads g_zA (z2)
// ---------------------------------------------------------------------------
__global__ void __launch_bounds__(128)
pass3_lite(const int* __restrict__ nbr, const int* __restrict__ drivers) {
    unsigned gid = blockIdx.x * blockDim.x + threadIdx.x;
    if (gid >= (unsigned)NDRVN * DD * BB) return;
    int job = gid >> 5;
    int b = gid & 31;

    int d = job >> 4;
    int j = job & 15;
    int m = __ldg(&nbr[__ldg(&drivers[d]) * DD + j]);

    float v[DD];
    const int* nb = nbr + m * DD;
    #pragma unroll
    for (int k = 0; k < DD; k++) {
        int idx = __ldg(&nb[k]);
        v[k] = __ldg(&g_zA[idx * BB + b]);
    }
    g_z3[job * BB + b] = conv_stack_c(v);
}

// ---------------------------------------------------------------------------
// Pass 4 (lite): only the 500 driver nodes, inputs direct from g_z3
// ---------------------------------------------------------------------------
__global__ void __launch_bounds__(128)
pass4_lite() {
    unsigned gid = blockIdx.x * blockDim.x + threadIdx.x;
    if (gid >= (unsigned)NDRVN * BB) return;
    int d = gid >> 5;
    int b = gid & 31;

    float v[DD];
    #pragma unroll
    for (int k = 0; k < DD; k++)
        v[k] = __ldg(&g_z3[(d * DD + k) * BB + b]);
    g_zf[d * BB + b] = conv_stack_c(v);
}

// ---------------------------------------------------------------------------
__global__ void zero_kernel(float4* __restrict__ out, int n4) {
    int i = blockIdx.x * blockDim.x + threadIdx.x;
    if (i < n4) out[i] = make_float4(0.f, 0.f, 0.f, 0.f);
}

// ---------------------------------------------------------------------------
// Masked softmax over driver columns; reads g_zf [500][B].
// Z = sum_drivers exp(z-m) + (N-NDRV)*exp(-m),  m = max(0, max_drivers z)
// ---------------------------------------------------------------------------
__global__ void softmax_kernel(const int* __restrict__ drivers,
                               float* __restrict__ out) {
    __shared__ float red[512];
    int b = blockIdx.x;
    int t = threadIdx.x;

    float myv = 0.0f;
    int drv = -1;
    float mval = -INFINITY;
    if (t < NDRVN) {
        drv = drivers[t];
        myv = g_zf[t * BB + b];
        mval = myv;
    }
    red[t] = mval;
    __syncthreads();
    #pragma unroll
    for (int s = 256; s > 0; s >>= 1) {
        if (t < s) red[t] = fmaxf(red[t], red[t + s]);
        __syncthreads();
    }
    float m = fmaxf(red[0], 0.0f);
    __syncthreads();

    float e = (t < NDRVN) ? expf(myv - m) : 0.0f;
    red[t] = e;
    __syncthreads();
    #pragma unroll
    for (int s = 256; s > 0; s >>= 1) {
        if (t < s) red[t] += red[t + s];
        __syncthreads();
    }
    float Z = red[0] + (float)(NNODES - NDRVN) * expf(-m);

    if (t < NDRVN) out[b * NNODES + drv] = e / Z;
}

// ---------------------------------------------------------------------------
extern "C" void kernel_launch(void* const* d_in, const int* in_sizes, int n_in,
                              void* d_out, int out_size) {
    const float* x       = (const float*)d_in[0];
    const int*   nbr     = (const int*)  d_in[1];
    const int*   drivers = (const int*)  d_in[2];
    const float* w_first = (const float*)d_in[4];
    const float* b_first = (const float*)d_in[5];
    const float* w_mid   = (const float*)d_in[6];
    const float* b_mid   = (const float*)d_in[7];
    const float* w_last  = (const float*)d_in[8];
    const float* b_last  = (const float*)d_in[9];
    float* out = (float*)d_out;

    // Weights -> __constant__ (graph-capturable D2D memcpy nodes)
    cudaMemcpyToSymbolAsync(c_wf, w_first, FEAT * 3 * sizeof(float), 0, cudaMemcpyDeviceToDevice);
    cudaMemcpyToSymbolAsync(c_bf, b_first, FEAT * sizeof(float), 0, cudaMemcpyDeviceToDevice);
    cudaMemcpyToSymbolAsync(c_wm, w_mid, NMID * FEAT * FEAT * 3 * sizeof(float), 0, cudaMemcpyDeviceToDevice);
    cudaMemcpyToSymbolAsync(c_bm, b_mid, NMID * FEAT * sizeof(float), 0, cudaMemcpyDeviceToDevice);
    cudaMemcpyToSymbolAsync(c_wl, w_last, FEAT * 3 * sizeof(float), 0, cudaMemcpyDeviceToDevice);
    cudaMemcpyToSymbolAsync(c_bl, b_last, sizeof(float), 0, cudaMemcpyDeviceToDevice);

    // Independent prologue
    int n4 = NNODES * BB / 4;
    zero_kernel<<<(n4 + 255) / 256, 256>>>((float4*)out, n4);
    transpose_kernel<<<(NNODES + 31) / 32, dim3(32, 32)>>>(x);

    const int blk = 128;
    const int grid_sc = (NNODES * BB) / blk;   // exact: 12500

    // Passes 1-2: full graph, scalar constant-weight body.  zA -> zB -> zA
    pass_const<0><<<grid_sc, blk>>>(nbr);
    pass_const<1><<<grid_sc, blk>>>(nbr);

    // Pass 3: drivers' neighbors only
    const int grid3 = (NDRVN * DD * BB + blk - 1) / blk;
    pass3_lite<<<grid3, blk>>>(nbr, drivers);

    // Pass 4: drivers only
    const int grid4 = (NDRVN * BB + blk - 1) / blk;
    pass4_lite<<<grid4, blk>>>();

    softmax_kernel<<<BB, 512>>>(drivers, out);
}